// round 3
// baseline (speedup 1.0000x reference)
#include <cuda_runtime.h>
#include <math.h>

#define BATCH 1024
#define WARPS_PER_BLOCK 8
#define BLOCK (WARPS_PER_BLOCK * 32)
#define MAX_STEPS 128

// Folded decoder: w = pW3^T @ dW (64), c = dW . pb3
__device__ float g_w[64];
__device__ float g_c[1];

__global__ void precompute_kernel(const float* __restrict__ dW,
                                  const float* __restrict__ pW3,
                                  const float* __restrict__ pb3) {
    int j = threadIdx.x;  // 0..63
    float acc = 0.0f;
    #pragma unroll 8
    for (int i = 0; i < 64; ++i) acc = fmaf(dW[i], pW3[i * 64 + j], acc);
    g_w[j] = acc;
    if (j == 0) {
        float c = 0.0f;
        #pragma unroll 8
        for (int i = 0; i < 64; ++i) c = fmaf(dW[i], pb3[i], c);
        g_c[0] = c;
    }
}

// Warp sum via butterfly (redux.f32 not available at this compile target)
__device__ __forceinline__ float warp_sum(float v) {
    #pragma unroll
    for (int off = 16; off; off >>= 1)
        v += __shfl_xor_sync(0xffffffffu, v, off);
    return v;
}

// Hardware MUFU tanh (sm_75+): ~16 cyc, max abs err ~5e-4
__device__ __forceinline__ float fast_tanh(float x) {
    float r;
    asm("tanh.approx.f32 %0, %1;" : "=f"(r) : "f"(x));
    return r;
}

// theta MLP layer2+3: pre = tW1a*tau + tb1 precomputed.
// Returns sum(tw3 * h2) broadcast to all lanes (bias tb3 added by caller).
__device__ __forceinline__ float theta_eval(float pre, float ys, float tbw,
                                            float tb2r, float tw3r,
                                            const float* __restrict__ sT2T,
                                            int lane) {
    float h = fast_tanh(fmaf(tbw, ys, pre));
    float a0 = tb2r, a1 = 0.0f, a2 = 0.0f, a3 = 0.0f;
    #pragma unroll
    for (int k = 0; k < 32; k += 4) {
        float h0 = __shfl_sync(0xffffffffu, h, k + 0);
        float h1 = __shfl_sync(0xffffffffu, h, k + 1);
        float h2s = __shfl_sync(0xffffffffu, h, k + 2);
        float h3 = __shfl_sync(0xffffffffu, h, k + 3);
        a0 = fmaf(sT2T[(k + 0) * 33 + lane], h0, a0);
        a1 = fmaf(sT2T[(k + 1) * 33 + lane], h1, a1);
        a2 = fmaf(sT2T[(k + 2) * 33 + lane], h2s, a2);
        a3 = fmaf(sT2T[(k + 3) * 33 + lane], h3, a3);
    }
    float h2 = fast_tanh((a0 + a1) + (a2 + a3));
    return warp_sum(tw3r * h2);
}

__global__ void __launch_bounds__(BLOCK, 1)
neural_ode_kernel(const float* __restrict__ t,
                  const float* __restrict__ pW1, const float* __restrict__ pb1,
                  const float* __restrict__ pW2, const float* __restrict__ pb2,
                  const float* __restrict__ db,
                  const float* __restrict__ tW1, const float* __restrict__ tb1,
                  const float* __restrict__ tW2, const float* __restrict__ tb2,
                  const float* __restrict__ tW3, const float* __restrict__ tb3,
                  float* __restrict__ out) {
    __shared__ float sW2T[64 * 65];   // pW2 transposed, padded
    __shared__ float sT2T[32 * 33];   // tW2 transposed, padded
    __shared__ float sW1a[64], sW1b[64], sPb1[64], sPb2[64], sw[64];
    __shared__ float sT1a[32], sT1b[32], sTb1[32], sTb2[32], sTw3[32];
    __shared__ float sScal[3];        // c_fold, db0, tb3_0

    int tid = threadIdx.x;
    for (int idx = tid; idx < 4096; idx += BLOCK) {
        int j = idx >> 6, k = idx & 63;
        sW2T[k * 65 + j] = pW2[idx];
    }
    for (int idx = tid; idx < 1024; idx += BLOCK) {
        int j = idx >> 5, k = idx & 31;
        sT2T[k * 33 + j] = tW2[idx];
    }
    if (tid < 64) {
        sW1a[tid] = pW1[2 * tid];
        sW1b[tid] = pW1[2 * tid + 1];
        sPb1[tid] = pb1[tid];
        sPb2[tid] = pb2[tid];
        sw[tid]   = g_w[tid];
    }
    if (tid < 32) {
        sT1a[tid] = tW1[2 * tid];
        sT1b[tid] = tW1[2 * tid + 1];
        sTb1[tid] = tb1[tid];
        sTb2[tid] = tb2[tid];
        sTw3[tid] = tW3[tid];
    }
    if (tid == 0) {
        sScal[0] = g_c[0];
        sScal[1] = db[0];
        sScal[2] = tb3[0];
    }
    __syncthreads();

    int warp = tid >> 5, lane = tid & 31;
    int b = blockIdx.x * WARPS_PER_BLOCK + warp;

    float w1a_lo = sW1a[lane],       w1b_lo = sW1b[lane];
    float w1a_hi = sW1a[lane + 32],  w1b_hi = sW1b[lane + 32];
    float b1_lo  = sPb1[lane],       b1_hi  = sPb1[lane + 32];
    float b2_lo  = sPb2[lane],       b2_hi  = sPb2[lane + 32];
    float w_lo   = sw[lane],         w_hi   = sw[lane + 32];
    float ta  = sT1a[lane], tbw = sT1b[lane], tb1r = sTb1[lane];
    float tb2r = sTb2[lane], tw3r = sTw3[lane];
    float cfold = sScal[0], db0 = sScal[1], tb30 = sScal[2];

    const float C2 = 0.2f, C3 = 0.3f, C4 = 0.8f, C5 = (float)(8.0 / 9.0);
    const float A21 = 0.2f;
    const float A31 = (float)(3.0 / 40.0),   A32 = (float)(9.0 / 40.0);
    const float A41 = (float)(44.0 / 45.0),  A42 = (float)(-56.0 / 15.0), A43 = (float)(32.0 / 9.0);
    const float A51 = (float)(19372.0 / 6561.0), A52 = (float)(-25360.0 / 2187.0);
    const float A53 = (float)(64448.0 / 6561.0), A54 = (float)(-212.0 / 729.0);
    const float A61 = (float)(9017.0 / 3168.0),  A62 = (float)(-355.0 / 33.0);
    const float A63 = (float)(46732.0 / 5247.0), A64 = (float)(49.0 / 176.0);
    const float A65 = (float)(-5103.0 / 18656.0);
    const float B1 = (float)(35.0 / 384.0), B3 = (float)(500.0 / 1113.0);
    const float B4 = (float)(125.0 / 192.0), B5 = (float)(-2187.0 / 6784.0);
    const float B6 = (float)(11.0 / 84.0);
    const float E1 = (float)(35.0 / 384.0 - 5179.0 / 57600.0);
    const float E3 = (float)(500.0 / 1113.0 - 7571.0 / 16695.0);
    const float E4 = (float)(125.0 / 192.0 - 393.0 / 640.0);
    const float E5 = (float)(-2187.0 / 6784.0 + 92097.0 / 339200.0);
    const float E6 = (float)(11.0 / 84.0 - 187.0 / 2100.0);
    const float E7 = (float)(-1.0 / 40.0);
    const float RTOL = 1e-3f, ATOL = 1e-6f;
    const float SAFETY = 0.9f, FMIN = 0.2f, FMAX = 10.0f;

    float t1 = t[b];
    float tau = 0.0f, y = 0.0f, dt = 0.01f;

    for (int it = 0; it < MAX_STEPS; ++it) {
        float remaining = t1 - tau;
        if (remaining <= 1e-10f) break;
        float dt_eff = fminf(dt, remaining);

        float taus[6];
        taus[0] = tau;
        taus[1] = tau + C2 * dt_eff;
        taus[2] = tau + C3 * dt_eff;
        taus[3] = tau + C4 * dt_eff;
        taus[4] = tau + C5 * dt_eff;
        taus[5] = tau + dt_eff;

        // theta layer-1 tau-parts
        float pre[6];
        #pragma unroll
        for (int s = 0; s < 6; ++s) pre[s] = fmaf(ta, taus[s], tb1r);

        // f1 does not depend on phi -> issue first, overlaps phi block
        float f1 = theta_eval(pre[0], y, tbw, tb2r, tw3r, sT2T, lane) + tb30;

        // ---- Batched phi for all 6 taus
        float h1lo[6], h1hi[6];
        #pragma unroll
        for (int s = 0; s < 6; ++s) {
            h1lo[s] = fast_tanh(fmaf(w1a_lo, t1, fmaf(w1b_lo, taus[s], b1_lo)));
            h1hi[s] = fast_tanh(fmaf(w1a_hi, t1, fmaf(w1b_hi, taus[s], b1_hi)));
        }
        float acc_lo[6], acc_hi[6];
        #pragma unroll
        for (int s = 0; s < 6; ++s) { acc_lo[s] = b2_lo; acc_hi[s] = b2_hi; }

        #pragma unroll 4
        for (int k = 0; k < 32; ++k) {
            float alo[6], ahi[6];
            #pragma unroll
            for (int s = 0; s < 6; ++s) {
                alo[s] = __shfl_sync(0xffffffffu, h1lo[s], k);
                ahi[s] = __shfl_sync(0xffffffffu, h1hi[s], k);
            }
            float wA = sW2T[k * 65 + lane];
            float wB = sW2T[(k + 32) * 65 + lane];
            float wC = sW2T[k * 65 + lane + 32];
            float wD = sW2T[(k + 32) * 65 + lane + 32];
            #pragma unroll
            for (int s = 0; s < 6; ++s) {
                acc_lo[s] = fmaf(wA, alo[s], fmaf(wB, ahi[s], acc_lo[s]));
                acc_hi[s] = fmaf(wC, alo[s], fmaf(wD, ahi[s], acc_hi[s]));
            }
        }
        float g[6];
        #pragma unroll
        for (int s = 0; s < 6; ++s) {
            float v = fmaf(w_lo, fast_tanh(acc_lo[s]), w_hi * fast_tanh(acc_hi[s]));
            g[s] = warp_sum(v) + cfold;
        }

        // ---- Sequential theta stages
        float k1 = fmaf(g[0], f1, db0);

        float y2 = fmaf(dt_eff, A21 * k1, y);
        float f2 = theta_eval(pre[1], y2, tbw, tb2r, tw3r, sT2T, lane) + tb30;
        float k2 = fmaf(g[1], f2, db0);

        float y3 = fmaf(dt_eff, fmaf(A31, k1, A32 * k2), y);
        float f3 = theta_eval(pre[2], y3, tbw, tb2r, tw3r, sT2T, lane) + tb30;
        float k3 = fmaf(g[2], f3, db0);

        float y4 = fmaf(dt_eff, fmaf(A41, k1, fmaf(A42, k2, A43 * k3)), y);
        float f4 = theta_eval(pre[3], y4, tbw, tb2r, tw3r, sT2T, lane) + tb30;
        float k4 = fmaf(g[3], f4, db0);

        float y5i = fmaf(dt_eff, fmaf(A51, k1, fmaf(A52, k2, fmaf(A53, k3, A54 * k4))), y);
        float f5 = theta_eval(pre[4], y5i, tbw, tb2r, tw3r, sT2T, lane) + tb30;
        float k5 = fmaf(g[4], f5, db0);

        float y6 = fmaf(dt_eff, fmaf(A61, k1, fmaf(A62, k2, fmaf(A63, k3, fmaf(A64, k4, A65 * k5)))), y);
        float f6 = theta_eval(pre[5], y6, tbw, tb2r, tw3r, sT2T, lane) + tb30;
        float k6 = fmaf(g[5], f6, db0);

        float y5 = fmaf(dt_eff,
                        fmaf(B1, k1, fmaf(B3, k3, fmaf(B4, k4, fmaf(B5, k5, B6 * k6)))),
                        y);
        float f7 = theta_eval(pre[5], y5, tbw, tb2r, tw3r, sT2T, lane) + tb30;
        float k7 = fmaf(g[5], f7, db0);

        float err = dt_eff *
            fmaf(E1, k1, fmaf(E3, k3, fmaf(E4, k4, fmaf(E5, k5, fmaf(E6, k6, E7 * k7)))));
        float scale = fmaf(RTOL, fmaxf(fabsf(y), fabsf(y5)), ATOL);
        float r = __fdividef(err, scale);
        float err_norm = sqrtf(fmaf(r, r, 1e-30f));

        bool accept = (err_norm <= 1.0f);
        float en = fmaxf(err_norm, 1e-10f);
        float factor = SAFETY * exp2f(-0.2f * __log2f(en));
        factor = fminf(fmaxf(factor, FMIN), FMAX);

        if (accept) {
            tau = tau + dt_eff;
            y = y5;
        }
        dt = fmaxf(dt_eff * factor, 1e-8f);
    }

    if (lane == 0) out[b] = y;
}

extern "C" void kernel_launch(void* const* d_in, const int* in_sizes, int n_in,
                              void* d_out, int out_size) {
    const float* t    = (const float*)d_in[0];
    const float* pW1  = (const float*)d_in[1];
    const float* pb1  = (const float*)d_in[2];
    const float* pW2  = (const float*)d_in[3];
    const float* pb2  = (const float*)d_in[4];
    const float* pW3  = (const float*)d_in[5];
    const float* pb3  = (const float*)d_in[6];
    const float* dW   = (const float*)d_in[7];
    const float* db   = (const float*)d_in[8];
    const float* tW1  = (const float*)d_in[9];
    const float* tb1  = (const float*)d_in[10];
    const float* tW2  = (const float*)d_in[11];
    const float* tb2  = (const float*)d_in[12];
    const float* tW3  = (const float*)d_in[13];
    const float* tb3  = (const float*)d_in[14];
    float* out = (float*)d_out;

    precompute_kernel<<<1, 64>>>(dW, pW3, pb3);
    neural_ode_kernel<<<BATCH / WARPS_PER_BLOCK, BLOCK>>>(
        t, pW1, pb1, pW2, pb2, db, tW1, tb1, tW2, tb2, tW3, tb3, out);
}

// round 4
// speedup vs baseline: 1.1181x; 1.1181x over previous
#include <cuda_runtime.h>
#include <math.h>

#define BATCH 1024
#define WARPS_PER_BLOCK 8
#define BLOCK (WARPS_PER_BLOCK * 32)
#define MAX_STEPS 128

// Grid tabulation of g(t1, tau): NG points, tau_j = (j-1)*h, h = t1/17
#define NG 20
#define NSEG 17

// Folded decoder: w = pW3^T @ dW (64), c = dW . pb3
__device__ float g_w[64];
__device__ float g_c[1];
// Tabulated g values per element
__device__ float g_grid[BATCH * NG];

__global__ void precompute_kernel(const float* __restrict__ dW,
                                  const float* __restrict__ pW3,
                                  const float* __restrict__ pb3) {
    int j = threadIdx.x;  // 0..63
    float acc = 0.0f;
    #pragma unroll 8
    for (int i = 0; i < 64; ++i) acc = fmaf(dW[i], pW3[i * 64 + j], acc);
    g_w[j] = acc;
    if (j == 0) {
        float c = 0.0f;
        #pragma unroll 8
        for (int i = 0; i < 64; ++i) c = fmaf(dW[i], pb3[i], c);
        g_c[0] = c;
    }
}

__device__ __forceinline__ float warp_sum(float v) {
    #pragma unroll
    for (int off = 16; off; off >>= 1)
        v += __shfl_xor_sync(0xffffffffu, v, off);
    return v;
}

// Hardware MUFU tanh (sm_75+): ~16 cyc, max abs err ~5e-4
__device__ __forceinline__ float fast_tanh(float x) {
    float r;
    asm("tanh.approx.f32 %0, %1;" : "=f"(r) : "f"(x));
    return r;
}

// ---------------------------------------------------------------------------
// Tabulation kernel: one warp per (element, 4 grid points). 5120 warps total.
// g(t1,tau) = w . tanh(pW2 @ tanh(pW1 @ [t1,tau] + pb1) + pb2) + c
// ---------------------------------------------------------------------------
__global__ void __launch_bounds__(BLOCK)
tabulate_kernel(const float* __restrict__ t,
                const float* __restrict__ pW1, const float* __restrict__ pb1,
                const float* __restrict__ pW2, const float* __restrict__ pb2) {
    __shared__ float sW2T[64 * 65];   // pW2 transposed, padded
    __shared__ float sW1a[64], sW1b[64], sPb1[64], sPb2[64], sw[64];
    __shared__ float sC[1];

    int tid = threadIdx.x;
    for (int idx = tid; idx < 4096; idx += BLOCK) {
        int j = idx >> 6, k = idx & 63;
        sW2T[k * 65 + j] = pW2[idx];
    }
    if (tid < 64) {
        sW1a[tid] = pW1[2 * tid];
        sW1b[tid] = pW1[2 * tid + 1];
        sPb1[tid] = pb1[tid];
        sPb2[tid] = pb2[tid];
        sw[tid]   = g_w[tid];
    }
    if (tid == 0) sC[0] = g_c[0];
    __syncthreads();

    int warp = tid >> 5, lane = tid & 31;
    int task = blockIdx.x * WARPS_PER_BLOCK + warp;  // 0..5119
    int b = task / 5;
    int j4 = (task % 5) * 4;                          // first of 4 grid points

    float w1a_lo = sW1a[lane],       w1b_lo = sW1b[lane];
    float w1a_hi = sW1a[lane + 32],  w1b_hi = sW1b[lane + 32];
    float b1_lo  = sPb1[lane],       b1_hi  = sPb1[lane + 32];
    float b2_lo  = sPb2[lane],       b2_hi  = sPb2[lane + 32];
    float w_lo   = sw[lane],         w_hi   = sw[lane + 32];
    float cfold  = sC[0];

    float t1 = t[b];
    float h = t1 * (1.0f / (float)NSEG);

    float taus[4];
    #pragma unroll
    for (int s = 0; s < 4; ++s) taus[s] = (float)(j4 + s - 1) * h;

    float h1lo[4], h1hi[4];
    #pragma unroll
    for (int s = 0; s < 4; ++s) {
        h1lo[s] = fast_tanh(fmaf(w1a_lo, t1, fmaf(w1b_lo, taus[s], b1_lo)));
        h1hi[s] = fast_tanh(fmaf(w1a_hi, t1, fmaf(w1b_hi, taus[s], b1_hi)));
    }
    float acc_lo[4], acc_hi[4];
    #pragma unroll
    for (int s = 0; s < 4; ++s) { acc_lo[s] = b2_lo; acc_hi[s] = b2_hi; }

    #pragma unroll 4
    for (int k = 0; k < 32; ++k) {
        float alo[4], ahi[4];
        #pragma unroll
        for (int s = 0; s < 4; ++s) {
            alo[s] = __shfl_sync(0xffffffffu, h1lo[s], k);
            ahi[s] = __shfl_sync(0xffffffffu, h1hi[s], k);
        }
        float wA = sW2T[k * 65 + lane];
        float wB = sW2T[(k + 32) * 65 + lane];
        float wC = sW2T[k * 65 + lane + 32];
        float wD = sW2T[(k + 32) * 65 + lane + 32];
        #pragma unroll
        for (int s = 0; s < 4; ++s) {
            acc_lo[s] = fmaf(wA, alo[s], fmaf(wB, ahi[s], acc_lo[s]));
            acc_hi[s] = fmaf(wC, alo[s], fmaf(wD, ahi[s], acc_hi[s]));
        }
    }
    float g[4];
    #pragma unroll
    for (int s = 0; s < 4; ++s) {
        float v = fmaf(w_lo, fast_tanh(acc_lo[s]), w_hi * fast_tanh(acc_hi[s]));
        g[s] = warp_sum(v) + cfold;
    }
    if (lane == 0) {
        #pragma unroll
        for (int s = 0; s < 4; ++s) g_grid[b * NG + j4 + s] = g[s];
    }
}

// ---------------------------------------------------------------------------
// theta MLP layer2+3 (32-wide). pre = tW1a*tau + tb1 precomputed per lane.
// ---------------------------------------------------------------------------
__device__ __forceinline__ float theta_eval(float pre, float ys, float tbw,
                                            float tb2r, float tw3r,
                                            const float* __restrict__ sT2T,
                                            int lane) {
    float hv = fast_tanh(fmaf(tbw, ys, pre));
    float a0 = tb2r, a1 = 0.0f, a2 = 0.0f, a3 = 0.0f;
    #pragma unroll
    for (int k = 0; k < 32; k += 4) {
        float h0 = __shfl_sync(0xffffffffu, hv, k + 0);
        float h1 = __shfl_sync(0xffffffffu, hv, k + 1);
        float h2s = __shfl_sync(0xffffffffu, hv, k + 2);
        float h3 = __shfl_sync(0xffffffffu, hv, k + 3);
        a0 = fmaf(sT2T[(k + 0) * 33 + lane], h0, a0);
        a1 = fmaf(sT2T[(k + 1) * 33 + lane], h1, a1);
        a2 = fmaf(sT2T[(k + 2) * 33 + lane], h2s, a2);
        a3 = fmaf(sT2T[(k + 3) * 33 + lane], h3, a3);
    }
    float h2 = fast_tanh((a0 + a1) + (a2 + a3));
    return warp_sum(tw3r * h2);
}

// 4-point Lagrange cubic interpolation of g at tau.  sGw = this warp's grid.
__device__ __forceinline__ float g_interp(const float* __restrict__ sGw,
                                          float tau, float inv_h) {
    float s = fmaf(tau, inv_h, 1.0f);
    float fi = floorf(s);
    int i = (int)fi;
    i = i < 1 ? 1 : (i > NSEG ? NSEG : i);
    float u = s - (float)i;
    float p0 = sGw[i - 1], p1 = sGw[i], p2 = sGw[i + 1], p3 = sGw[i + 2];
    float um1 = u - 1.0f, um2 = u - 2.0f, up1 = u + 1.0f;
    float w0 = (-1.0f / 6.0f) * u * um1 * um2;
    float w1 = 0.5f * up1 * um1 * um2;
    float w2 = -0.5f * up1 * u * um2;
    float w3 = (1.0f / 6.0f) * up1 * u * um1;
    return fmaf(w0, p0, fmaf(w1, p1, fmaf(w2, p2, w3 * p3)));
}

__global__ void __launch_bounds__(BLOCK, 1)
neural_ode_kernel(const float* __restrict__ t,
                  const float* __restrict__ db,
                  const float* __restrict__ tW1, const float* __restrict__ tb1,
                  const float* __restrict__ tW2, const float* __restrict__ tb2,
                  const float* __restrict__ tW3, const float* __restrict__ tb3,
                  float* __restrict__ out) {
    __shared__ float sT2T[32 * 33];   // tW2 transposed, padded
    __shared__ float sT1a[32], sT1b[32], sTb1[32], sTb2[32], sTw3[32];
    __shared__ float sScal[2];        // db0, tb3_0
    __shared__ float sG[WARPS_PER_BLOCK][NG];

    int tid = threadIdx.x;
    for (int idx = tid; idx < 1024; idx += BLOCK) {
        int j = idx >> 5, k = idx & 31;
        sT2T[k * 33 + j] = tW2[idx];
    }
    if (tid < 32) {
        sT1a[tid] = tW1[2 * tid];
        sT1b[tid] = tW1[2 * tid + 1];
        sTb1[tid] = tb1[tid];
        sTb2[tid] = tb2[tid];
        sTw3[tid] = tW3[tid];
    }
    if (tid == 0) {
        sScal[0] = db[0];
        sScal[1] = tb3[0];
    }

    int warp = tid >> 5, lane = tid & 31;
    int b = blockIdx.x * WARPS_PER_BLOCK + warp;

    // Load this element's g-grid into shared
    if (lane < NG) sG[warp][lane] = g_grid[b * NG + lane];
    __syncthreads();
    const float* sGw = sG[warp];

    float ta  = sT1a[lane], tbw = sT1b[lane], tb1r = sTb1[lane];
    float tb2r = sTb2[lane], tw3r = sTw3[lane];
    float db0 = sScal[0], tb30 = sScal[1];

    const float C2 = 0.2f, C3 = 0.3f, C4 = 0.8f, C5 = (float)(8.0 / 9.0);
    const float A21 = 0.2f;
    const float A31 = (float)(3.0 / 40.0),   A32 = (float)(9.0 / 40.0);
    const float A41 = (float)(44.0 / 45.0),  A42 = (float)(-56.0 / 15.0), A43 = (float)(32.0 / 9.0);
    const float A51 = (float)(19372.0 / 6561.0), A52 = (float)(-25360.0 / 2187.0);
    const float A53 = (float)(64448.0 / 6561.0), A54 = (float)(-212.0 / 729.0);
    const float A61 = (float)(9017.0 / 3168.0),  A62 = (float)(-355.0 / 33.0);
    const float A63 = (float)(46732.0 / 5247.0), A64 = (float)(49.0 / 176.0);
    const float A65 = (float)(-5103.0 / 18656.0);
    const float B1 = (float)(35.0 / 384.0), B3 = (float)(500.0 / 1113.0);
    const float B4 = (float)(125.0 / 192.0), B5 = (float)(-2187.0 / 6784.0);
    const float B6 = (float)(11.0 / 84.0);
    const float E1 = (float)(35.0 / 384.0 - 5179.0 / 57600.0);
    const float E3 = (float)(500.0 / 1113.0 - 7571.0 / 16695.0);
    const float E4 = (float)(125.0 / 192.0 - 393.0 / 640.0);
    const float E5 = (float)(-2187.0 / 6784.0 + 92097.0 / 339200.0);
    const float E6 = (float)(11.0 / 84.0 - 187.0 / 2100.0);
    const float E7 = (float)(-1.0 / 40.0);
    const float RTOL = 1e-3f, ATOL = 1e-6f;
    const float SAFETY = 0.9f, FMIN = 0.2f, FMAX = 10.0f;

    float t1 = t[b];
    float inv_h = __fdividef((float)NSEG, t1);
    float tau = 0.0f, y = 0.0f, dt = 0.01f;

    // FSAL: f1 = theta(tau, y); recomputed only via the f7 hand-off.
    float f1 = theta_eval(tb1r, 0.0f, tbw, tb2r, tw3r, sT2T, lane) + tb30;

    for (int it = 0; it < MAX_STEPS; ++it) {
        float remaining = t1 - tau;
        if (remaining <= 1e-10f) break;
        float dt_eff = fminf(dt, remaining);

        float taus[6];
        taus[0] = tau;
        taus[1] = tau + C2 * dt_eff;
        taus[2] = tau + C3 * dt_eff;
        taus[3] = tau + C4 * dt_eff;
        taus[4] = tau + C5 * dt_eff;
        taus[5] = tau + dt_eff;

        // g at all 6 stage taus via cubic interpolation (independent, overlap)
        float g[6];
        #pragma unroll
        for (int s = 0; s < 6; ++s) g[s] = g_interp(sGw, taus[s], inv_h);

        // theta layer-1 tau-parts for stages 2..7
        float pre[6];
        #pragma unroll
        for (int s = 0; s < 6; ++s) pre[s] = fmaf(ta, taus[s], tb1r);

        float k1 = fmaf(g[0], f1, db0);

        float y2 = fmaf(dt_eff, A21 * k1, y);
        float f2 = theta_eval(pre[1], y2, tbw, tb2r, tw3r, sT2T, lane) + tb30;
        float k2 = fmaf(g[1], f2, db0);

        float y3 = fmaf(dt_eff, fmaf(A31, k1, A32 * k2), y);
        float f3 = theta_eval(pre[2], y3, tbw, tb2r, tw3r, sT2T, lane) + tb30;
        float k3 = fmaf(g[2], f3, db0);

        float y4 = fmaf(dt_eff, fmaf(A41, k1, fmaf(A42, k2, A43 * k3)), y);
        float f4 = theta_eval(pre[3], y4, tbw, tb2r, tw3r, sT2T, lane) + tb30;
        float k4 = fmaf(g[3], f4, db0);

        float y5i = fmaf(dt_eff, fmaf(A51, k1, fmaf(A52, k2, fmaf(A53, k3, A54 * k4))), y);
        float f5 = theta_eval(pre[4], y5i, tbw, tb2r, tw3r, sT2T, lane) + tb30;
        float k5 = fmaf(g[4], f5, db0);

        float y6 = fmaf(dt_eff, fmaf(A61, k1, fmaf(A62, k2, fmaf(A63, k3, fmaf(A64, k4, A65 * k5)))), y);
        float f6 = theta_eval(pre[5], y6, tbw, tb2r, tw3r, sT2T, lane) + tb30;
        float k6 = fmaf(g[5], f6, db0);

        float y5 = fmaf(dt_eff,
                        fmaf(B1, k1, fmaf(B3, k3, fmaf(B4, k4, fmaf(B5, k5, B6 * k6)))),
                        y);
        float f7 = theta_eval(pre[5], y5, tbw, tb2r, tw3r, sT2T, lane) + tb30;
        float k7 = fmaf(g[5], f7, db0);

        float err = dt_eff *
            fmaf(E1, k1, fmaf(E3, k3, fmaf(E4, k4, fmaf(E5, k5, fmaf(E6, k6, E7 * k7)))));
        float scale = fmaf(RTOL, fmaxf(fabsf(y), fabsf(y5)), ATOL);
        float r = __fdividef(err, scale);
        float err_norm = sqrtf(fmaf(r, r, 1e-30f));

        bool accept = (err_norm <= 1.0f);
        float en = fmaxf(err_norm, 1e-10f);
        float factor = SAFETY * exp2f(-0.2f * __log2f(en));
        factor = fminf(fmaxf(factor, FMIN), FMAX);

        if (accept) {
            tau = tau + dt_eff;
            y = y5;
            f1 = f7;   // FSAL hand-off: theta(tau+dt_eff, y5) == next step's f1
        }
        dt = fmaxf(dt_eff * factor, 1e-8f);
    }

    if (lane == 0) out[b] = y;
}

extern "C" void kernel_launch(void* const* d_in, const int* in_sizes, int n_in,
                              void* d_out, int out_size) {
    const float* t    = (const float*)d_in[0];
    const float* pW1  = (const float*)d_in[1];
    const float* pb1  = (const float*)d_in[2];
    const float* pW2  = (const float*)d_in[3];
    const float* pb2  = (const float*)d_in[4];
    const float* pW3  = (const float*)d_in[5];
    const float* pb3  = (const float*)d_in[6];
    const float* dW   = (const float*)d_in[7];
    const float* db   = (const float*)d_in[8];
    const float* tW1  = (const float*)d_in[9];
    const float* tb1  = (const float*)d_in[10];
    const float* tW2  = (const float*)d_in[11];
    const float* tb2  = (const float*)d_in[12];
    const float* tW3  = (const float*)d_in[13];
    const float* tb3  = (const float*)d_in[14];
    float* out = (float*)d_out;

    precompute_kernel<<<1, 64>>>(dW, pW3, pb3);
    tabulate_kernel<<<(BATCH * 5) / WARPS_PER_BLOCK, BLOCK>>>(t, pW1, pb1, pW2, pb2);
    neural_ode_kernel<<<BATCH / WARPS_PER_BLOCK, BLOCK>>>(
        t, db, tW1, tb1, tW2, tb2, tW3, tb3, out);
}

// round 5
// speedup vs baseline: 1.1297x; 1.0104x over previous
#include <cuda_runtime.h>
#include <math.h>

#define BATCH 1024
#define WARPS_PER_BLOCK 8
#define BLOCK (WARPS_PER_BLOCK * 32)
#define MAX_STEPS 128

// Grid tabulation of g(t1, tau): NG points, tau_j = (j-1)*h, h = t1/17
#define NG 20
#define NSEG 17

// Tabulated g values per element
__device__ float g_grid[BATCH * NG];

__device__ __forceinline__ float warp_sum(float v) {
    #pragma unroll
    for (int off = 16; off; off >>= 1)
        v += __shfl_xor_sync(0xffffffffu, v, off);
    return v;
}

// Hardware MUFU tanh (sm_75+): ~16 cyc, max abs err ~5e-4
__device__ __forceinline__ float fast_tanh(float x) {
    float r;
    asm("tanh.approx.f32 %0, %1;" : "=f"(r) : "f"(x));
    return r;
}

// ---------------------------------------------------------------------------
// Tabulation kernel: one warp per (element, 4 grid points). 5120 warps total.
// g(t1,tau) = w . tanh(pW2 @ tanh(pW1 @ [t1,tau] + pb1) + pb2) + c
// where w = pW3^T @ dW and c = dW . pb3 are folded IN-BLOCK (no separate
// precompute launch — that cost 10us of serial latency).
// ---------------------------------------------------------------------------
__global__ void __launch_bounds__(BLOCK)
tabulate_kernel(const float* __restrict__ t,
                const float* __restrict__ pW1, const float* __restrict__ pb1,
                const float* __restrict__ pW2, const float* __restrict__ pb2,
                const float* __restrict__ pW3, const float* __restrict__ pb3,
                const float* __restrict__ dW) {
    __shared__ float sW2T[64 * 65];   // pW2 transposed, padded
    __shared__ float sW1a[64], sW1b[64], sPb1[64], sPb2[64], sw[64];
    __shared__ float sC[1];

    int tid = threadIdx.x;
    for (int idx = tid; idx < 4096; idx += BLOCK) {
        int j = idx >> 6, k = idx & 63;
        sW2T[k * 65 + j] = pW2[idx];
    }
    if (tid < 64) {
        sW1a[tid] = pW1[2 * tid];
        sW1b[tid] = pW1[2 * tid + 1];
        sPb1[tid] = pb1[tid];
        sPb2[tid] = pb2[tid];
        // fold decoder through pW3: w_j = sum_i dW[i] * pW3[i][j]
        float acc = 0.0f;
        #pragma unroll 8
        for (int i = 0; i < 64; ++i) acc = fmaf(dW[i], pW3[i * 64 + tid], acc);
        sw[tid] = acc;
    }
    if (tid == 0) {
        float c = 0.0f;
        #pragma unroll 8
        for (int i = 0; i < 64; ++i) c = fmaf(dW[i], pb3[i], c);
        sC[0] = c;
    }
    __syncthreads();

    int warp = tid >> 5, lane = tid & 31;
    int task = blockIdx.x * WARPS_PER_BLOCK + warp;  // 0..5119
    int b = task / 5;
    int j4 = (task % 5) * 4;                          // first of 4 grid points

    float w1a_lo = sW1a[lane],       w1b_lo = sW1b[lane];
    float w1a_hi = sW1a[lane + 32],  w1b_hi = sW1b[lane + 32];
    float b1_lo  = sPb1[lane],       b1_hi  = sPb1[lane + 32];
    float b2_lo  = sPb2[lane],       b2_hi  = sPb2[lane + 32];
    float w_lo   = sw[lane],         w_hi   = sw[lane + 32];
    float cfold  = sC[0];

    float t1 = t[b];
    float h = t1 * (1.0f / (float)NSEG);

    float taus[4];
    #pragma unroll
    for (int s = 0; s < 4; ++s) taus[s] = (float)(j4 + s - 1) * h;

    float h1lo[4], h1hi[4];
    #pragma unroll
    for (int s = 0; s < 4; ++s) {
        h1lo[s] = fast_tanh(fmaf(w1a_lo, t1, fmaf(w1b_lo, taus[s], b1_lo)));
        h1hi[s] = fast_tanh(fmaf(w1a_hi, t1, fmaf(w1b_hi, taus[s], b1_hi)));
    }
    float acc_lo[4], acc_hi[4];
    #pragma unroll
    for (int s = 0; s < 4; ++s) { acc_lo[s] = b2_lo; acc_hi[s] = b2_hi; }

    #pragma unroll 4
    for (int k = 0; k < 32; ++k) {
        float alo[4], ahi[4];
        #pragma unroll
        for (int s = 0; s < 4; ++s) {
            alo[s] = __shfl_sync(0xffffffffu, h1lo[s], k);
            ahi[s] = __shfl_sync(0xffffffffu, h1hi[s], k);
        }
        float wA = sW2T[k * 65 + lane];
        float wB = sW2T[(k + 32) * 65 + lane];
        float wC = sW2T[k * 65 + lane + 32];
        float wD = sW2T[(k + 32) * 65 + lane + 32];
        #pragma unroll
        for (int s = 0; s < 4; ++s) {
            acc_lo[s] = fmaf(wA, alo[s], fmaf(wB, ahi[s], acc_lo[s]));
            acc_hi[s] = fmaf(wC, alo[s], fmaf(wD, ahi[s], acc_hi[s]));
        }
    }
    float g[4];
    #pragma unroll
    for (int s = 0; s < 4; ++s) {
        float v = fmaf(w_lo, fast_tanh(acc_lo[s]), w_hi * fast_tanh(acc_hi[s]));
        g[s] = warp_sum(v) + cfold;
    }
    if (lane == 0) {
        #pragma unroll
        for (int s = 0; s < 4; ++s) g_grid[b * NG + j4 + s] = g[s];
    }
}

// ---------------------------------------------------------------------------
// theta MLP layer2+3 (32-wide). pre = tW1a*tau + tb1 precomputed per lane.
// 8 accumulators x 4 FMAs: shorter dependent chain behind each shfl batch.
// ---------------------------------------------------------------------------
__device__ __forceinline__ float theta_eval(float pre, float ys, float tbw,
                                            float tb2r, float tw3r,
                                            const float* __restrict__ sT2T,
                                            int lane) {
    float hv = fast_tanh(fmaf(tbw, ys, pre));
    float a[8];
    a[0] = tb2r;
    #pragma unroll
    for (int i = 1; i < 8; ++i) a[i] = 0.0f;
    #pragma unroll
    for (int k = 0; k < 32; k += 8) {
        float hb[8];
        #pragma unroll
        for (int i = 0; i < 8; ++i)
            hb[i] = __shfl_sync(0xffffffffu, hv, k + i);
        #pragma unroll
        for (int i = 0; i < 8; ++i)
            a[i] = fmaf(sT2T[(k + i) * 33 + lane], hb[i], a[i]);
    }
    float s01 = a[0] + a[1], s23 = a[2] + a[3];
    float s45 = a[4] + a[5], s67 = a[6] + a[7];
    float h2 = fast_tanh((s01 + s23) + (s45 + s67));
    return warp_sum(tw3r * h2);
}

// 4-point Lagrange cubic interpolation of g at tau.  sGw = this warp's grid.
__device__ __forceinline__ float g_interp(const float* __restrict__ sGw,
                                          float tau, float inv_h) {
    float s = fmaf(tau, inv_h, 1.0f);
    float fi = floorf(s);
    int i = (int)fi;
    i = i < 1 ? 1 : (i > NSEG ? NSEG : i);
    float u = s - (float)i;
    float p0 = sGw[i - 1], p1 = sGw[i], p2 = sGw[i + 1], p3 = sGw[i + 2];
    float um1 = u - 1.0f, um2 = u - 2.0f, up1 = u + 1.0f;
    float w0 = (-1.0f / 6.0f) * u * um1 * um2;
    float w1 = 0.5f * up1 * um1 * um2;
    float w2 = -0.5f * up1 * u * um2;
    float w3 = (1.0f / 6.0f) * up1 * u * um1;
    return fmaf(w0, p0, fmaf(w1, p1, fmaf(w2, p2, w3 * p3)));
}

__global__ void __launch_bounds__(BLOCK, 1)
neural_ode_kernel(const float* __restrict__ t,
                  const float* __restrict__ db,
                  const float* __restrict__ tW1, const float* __restrict__ tb1,
                  const float* __restrict__ tW2, const float* __restrict__ tb2,
                  const float* __restrict__ tW3, const float* __restrict__ tb3,
                  float* __restrict__ out) {
    __shared__ float sT2T[32 * 33];   // tW2 transposed, padded
    __shared__ float sT1a[32], sT1b[32], sTb1[32], sTb2[32], sTw3[32];
    __shared__ float sScal[2];        // db0, tb3_0
    __shared__ float sG[WARPS_PER_BLOCK][NG];

    int tid = threadIdx.x;
    for (int idx = tid; idx < 1024; idx += BLOCK) {
        int j = idx >> 5, k = idx & 31;
        sT2T[k * 33 + j] = tW2[idx];
    }
    if (tid < 32) {
        sT1a[tid] = tW1[2 * tid];
        sT1b[tid] = tW1[2 * tid + 1];
        sTb1[tid] = tb1[tid];
        sTb2[tid] = tb2[tid];
        sTw3[tid] = tW3[tid];
    }
    if (tid == 0) {
        sScal[0] = db[0];
        sScal[1] = tb3[0];
    }

    int warp = tid >> 5, lane = tid & 31;
    int b = blockIdx.x * WARPS_PER_BLOCK + warp;

    if (lane < NG) sG[warp][lane] = g_grid[b * NG + lane];
    __syncthreads();
    const float* sGw = sG[warp];

    float ta  = sT1a[lane], tbw = sT1b[lane], tb1r = sTb1[lane];
    float tb2r = sTb2[lane], tw3r = sTw3[lane];
    float db0 = sScal[0], tb30 = sScal[1];

    const float C2 = 0.2f, C3 = 0.3f, C4 = 0.8f, C5 = (float)(8.0 / 9.0);
    const float A21 = 0.2f;
    const float A31 = (float)(3.0 / 40.0),   A32 = (float)(9.0 / 40.0);
    const float A41 = (float)(44.0 / 45.0),  A42 = (float)(-56.0 / 15.0), A43 = (float)(32.0 / 9.0);
    const float A51 = (float)(19372.0 / 6561.0), A52 = (float)(-25360.0 / 2187.0);
    const float A53 = (float)(64448.0 / 6561.0), A54 = (float)(-212.0 / 729.0);
    const float A61 = (float)(9017.0 / 3168.0),  A62 = (float)(-355.0 / 33.0);
    const float A63 = (float)(46732.0 / 5247.0), A64 = (float)(49.0 / 176.0);
    const float A65 = (float)(-5103.0 / 18656.0);
    const float B1 = (float)(35.0 / 384.0), B3 = (float)(500.0 / 1113.0);
    const float B4 = (float)(125.0 / 192.0), B5 = (float)(-2187.0 / 6784.0);
    const float B6 = (float)(11.0 / 84.0);
    const float E1 = (float)(35.0 / 384.0 - 5179.0 / 57600.0);
    const float E3 = (float)(500.0 / 1113.0 - 7571.0 / 16695.0);
    const float E4 = (float)(125.0 / 192.0 - 393.0 / 640.0);
    const float E5 = (float)(-2187.0 / 6784.0 + 92097.0 / 339200.0);
    const float E6 = (float)(11.0 / 84.0 - 187.0 / 2100.0);
    const float E7 = (float)(-1.0 / 40.0);
    const float RTOL = 1e-3f, ATOL = 1e-6f;
    const float SAFETY = 0.9f, FMIN = 0.2f, FMAX = 10.0f;

    float t1 = t[b];
    float inv_h = __fdividef((float)NSEG, t1);
    float tau = 0.0f, y = 0.0f, dt = 0.01f;

    // FSAL: f1 = theta(tau, y); updated via the f7 hand-off on accept.
    float f1 = theta_eval(tb1r, 0.0f, tbw, tb2r, tw3r, sT2T, lane) + tb30;

    for (int it = 0; it < MAX_STEPS; ++it) {
        float remaining = t1 - tau;
        if (remaining <= 1e-10f) break;
        float dt_eff = fminf(dt, remaining);

        float taus[6];
        taus[0] = tau;
        taus[1] = tau + C2 * dt_eff;
        taus[2] = tau + C3 * dt_eff;
        taus[3] = tau + C4 * dt_eff;
        taus[4] = tau + C5 * dt_eff;
        taus[5] = tau + dt_eff;

        float g[6];
        #pragma unroll
        for (int s = 0; s < 6; ++s) g[s] = g_interp(sGw, taus[s], inv_h);

        float pre[6];
        #pragma unroll
        for (int s = 0; s < 6; ++s) pre[s] = fmaf(ta, taus[s], tb1r);

        float k1 = fmaf(g[0], f1, db0);

        float y2 = fmaf(dt_eff, A21 * k1, y);
        float f2 = theta_eval(pre[1], y2, tbw, tb2r, tw3r, sT2T, lane) + tb30;
        float k2 = fmaf(g[1], f2, db0);

        float y3 = fmaf(dt_eff, fmaf(A31, k1, A32 * k2), y);
        float f3 = theta_eval(pre[2], y3, tbw, tb2r, tw3r, sT2T, lane) + tb30;
        float k3 = fmaf(g[2], f3, db0);

        float y4 = fmaf(dt_eff, fmaf(A41, k1, fmaf(A42, k2, A43 * k3)), y);
        float f4 = theta_eval(pre[3], y4, tbw, tb2r, tw3r, sT2T, lane) + tb30;
        float k4 = fmaf(g[3], f4, db0);

        float y5i = fmaf(dt_eff, fmaf(A51, k1, fmaf(A52, k2, fmaf(A53, k3, A54 * k4))), y);
        float f5 = theta_eval(pre[4], y5i, tbw, tb2r, tw3r, sT2T, lane) + tb30;
        float k5 = fmaf(g[4], f5, db0);

        float y6 = fmaf(dt_eff, fmaf(A61, k1, fmaf(A62, k2, fmaf(A63, k3, fmaf(A64, k4, A65 * k5)))), y);
        float f6 = theta_eval(pre[5], y6, tbw, tb2r, tw3r, sT2T, lane) + tb30;
        float k6 = fmaf(g[5], f6, db0);

        float y5 = fmaf(dt_eff,
                        fmaf(B1, k1, fmaf(B3, k3, fmaf(B4, k4, fmaf(B5, k5, B6 * k6)))),
                        y);
        float f7 = theta_eval(pre[5], y5, tbw, tb2r, tw3r, sT2T, lane) + tb30;
        float k7 = fmaf(g[5], f7, db0);

        float err = dt_eff *
            fmaf(E1, k1, fmaf(E3, k3, fmaf(E4, k4, fmaf(E5, k5, fmaf(E6, k6, E7 * k7)))));
        float scale = fmaf(RTOL, fmaxf(fabsf(y), fabsf(y5)), ATOL);
        float r = __fdividef(err, scale);
        float err_norm = sqrtf(fmaf(r, r, 1e-30f));

        bool accept = (err_norm <= 1.0f);
        float en = fmaxf(err_norm, 1e-10f);
        float factor = SAFETY * exp2f(-0.2f * __log2f(en));
        factor = fminf(fmaxf(factor, FMIN), FMAX);

        if (accept) {
            tau = tau + dt_eff;
            y = y5;
            f1 = f7;   // FSAL hand-off
        }
        dt = fmaxf(dt_eff * factor, 1e-8f);
    }

    if (lane == 0) out[b] = y;
}

extern "C" void kernel_launch(void* const* d_in, const int* in_sizes, int n_in,
                              void* d_out, int out_size) {
    const float* t    = (const float*)d_in[0];
    const float* pW1  = (const float*)d_in[1];
    const float* pb1  = (const float*)d_in[2];
    const float* pW2  = (const float*)d_in[3];
    const float* pb2  = (const float*)d_in[4];
    const float* pW3  = (const float*)d_in[5];
    const float* pb3  = (const float*)d_in[6];
    const float* dW   = (const float*)d_in[7];
    const float* db   = (const float*)d_in[8];
    const float* tW1  = (const float*)d_in[9];
    const float* tb1  = (const float*)d_in[10];
    const float* tW2  = (const float*)d_in[11];
    const float* tb2  = (const float*)d_in[12];
    const float* tW3  = (const float*)d_in[13];
    const float* tb3  = (const float*)d_in[14];
    float* out = (float*)d_out;

    tabulate_kernel<<<(BATCH * 5) / WARPS_PER_BLOCK, BLOCK>>>(
        t, pW1, pb1, pW2, pb2, pW3, pb3, dW);
    neural_ode_kernel<<<BATCH / WARPS_PER_BLOCK, BLOCK>>>(
        t, db, tW1, tb1, tW2, tb2, tW3, tb3, out);
}

// round 7
// speedup vs baseline: 1.2827x; 1.1355x over previous
#include <cuda_runtime.h>
#include <math.h>

#define BATCH 1024
#define WARPS_PER_BLOCK 8
#define BLOCK (WARPS_PER_BLOCK * 32)
#define MAX_STEPS 128

// Grid tabulation of g(t1, tau): NG points, tau_j = (j-1)*h, h = t1/17
#define NG 20
#define NSEG 17

__device__ __forceinline__ float warp_sum(float v) {
    #pragma unroll
    for (int off = 16; off; off >>= 1)
        v += __shfl_xor_sync(0xffffffffu, v, off);
    return v;
}

// Hardware MUFU tanh (sm_75+): ~16 cyc, max abs err ~5e-4
__device__ __forceinline__ float fast_tanh(float x) {
    float r;
    asm("tanh.approx.f32 %0, %1;" : "=f"(r) : "f"(x));
    return r;
}

// theta MLP layer2+3 (32-wide). pre = tW1a*tau + tb1 precomputed per lane.
__device__ __forceinline__ float theta_eval(float pre, float ys, float tbw,
                                            float tb2r, float tw3r,
                                            const float* __restrict__ sT2T,
                                            int lane) {
    float hv = fast_tanh(fmaf(tbw, ys, pre));
    float a[8];
    a[0] = tb2r;
    #pragma unroll
    for (int i = 1; i < 8; ++i) a[i] = 0.0f;
    #pragma unroll
    for (int k = 0; k < 32; k += 8) {
        float hb[8];
        #pragma unroll
        for (int i = 0; i < 8; ++i)
            hb[i] = __shfl_sync(0xffffffffu, hv, k + i);
        #pragma unroll
        for (int i = 0; i < 8; ++i)
            a[i] = fmaf(sT2T[(k + i) * 33 + lane], hb[i], a[i]);
    }
    float s01 = a[0] + a[1], s23 = a[2] + a[3];
    float s45 = a[4] + a[5], s67 = a[6] + a[7];
    float h2 = fast_tanh((s01 + s23) + (s45 + s67));
    return warp_sum(tw3r * h2);
}

// 4-point Lagrange cubic interpolation of g at tau.
__device__ __forceinline__ float g_interp(const float* __restrict__ sGw,
                                          float tau, float inv_h) {
    float s = fmaf(tau, inv_h, 1.0f);
    float fi = floorf(s);
    int i = (int)fi;
    i = i < 1 ? 1 : (i > NSEG ? NSEG : i);
    float u = s - (float)i;
    float p0 = sGw[i - 1], p1 = sGw[i], p2 = sGw[i + 1], p3 = sGw[i + 2];
    float um1 = u - 1.0f, um2 = u - 2.0f, up1 = u + 1.0f;
    float w0 = (-1.0f / 6.0f) * u * um1 * um2;
    float w1 = 0.5f * up1 * um1 * um2;
    float w2 = -0.5f * up1 * u * um2;
    float w3 = (1.0f / 6.0f) * up1 * u * um1;
    return fmaf(w0, p0, fmaf(w1, p1, fmaf(w2, p2, w3 * p3)));
}

// ---------------------------------------------------------------------------
// Single fused kernel: stage weights -> fold decoder -> per-warp g-grid
// tabulation -> adaptive Dopri5 loop with FSAL + cubic-interp phi.
// ---------------------------------------------------------------------------
__global__ void __launch_bounds__(BLOCK, 1)
neural_ode_kernel(const float* __restrict__ t,
                  const float* __restrict__ pW1, const float* __restrict__ pb1,
                  const float* __restrict__ pW2, const float* __restrict__ pb2,
                  const float* __restrict__ pW3, const float* __restrict__ pb3,
                  const float* __restrict__ dW, const float* __restrict__ db,
                  const float* __restrict__ tW1, const float* __restrict__ tb1,
                  const float* __restrict__ tW2, const float* __restrict__ tb2,
                  const float* __restrict__ tW3, const float* __restrict__ tb3,
                  float* __restrict__ out) {
    __shared__ float sW2T[64 * 65];   // pW2 transposed, padded (prologue only)
    __shared__ float sT2T[32 * 33];   // tW2 transposed, padded
    __shared__ float sW1a[64], sW1b[64], sPb1[64], sPb2[64], sw[64];
    __shared__ float sFoldP[4][64];   // cooperative fold partials
    __shared__ float sCp[64];
    __shared__ float sT1a[32], sT1b[32], sTb1[32], sTb2[32], sTw3[32];
    __shared__ float sScal[3];        // c_fold, db0, tb3_0
    __shared__ float sG[WARPS_PER_BLOCK][NG];

    int tid = threadIdx.x;
    for (int idx = tid; idx < 4096; idx += BLOCK) {
        int j = idx >> 6, k = idx & 63;
        sW2T[k * 65 + j] = pW2[idx];
    }
    for (int idx = tid; idx < 1024; idx += BLOCK) {
        int j = idx >> 5, k = idx & 31;
        sT2T[k * 33 + j] = tW2[idx];
    }
    // Cooperative decoder fold: w_j = sum_i dW[i]*pW3[i][j]  (4 partials/out)
    {
        int q = tid >> 6, j = tid & 63;
        float p = 0.0f;
        #pragma unroll
        for (int i = 0; i < 16; ++i)
            p = fmaf(dW[q * 16 + i], pW3[(q * 16 + i) * 64 + j], p);
        sFoldP[q][j] = p;
    }
    if (tid < 64) {
        sW1a[tid] = pW1[2 * tid];
        sW1b[tid] = pW1[2 * tid + 1];
        sPb1[tid] = pb1[tid];
        sPb2[tid] = pb2[tid];
        sCp[tid]  = dW[tid] * pb3[tid];
    }
    if (tid < 32) {
        sT1a[tid] = tW1[2 * tid];
        sT1b[tid] = tW1[2 * tid + 1];
        sTb1[tid] = tb1[tid];
        sTb2[tid] = tb2[tid];
        sTw3[tid] = tW3[tid];
    }
    __syncthreads();
    if (tid < 64)
        sw[tid] = (sFoldP[0][tid] + sFoldP[1][tid]) + (sFoldP[2][tid] + sFoldP[3][tid]);
    if (tid == 0) {
        float c = 0.0f;
        #pragma unroll
        for (int i = 0; i < 64; ++i) c += sCp[i];
        sScal[0] = c;
        sScal[1] = db[0];
        sScal[2] = tb3[0];
    }
    __syncthreads();

    int warp = tid >> 5, lane = tid & 31;
    int b = blockIdx.x * WARPS_PER_BLOCK + warp;

    float w1a_lo = sW1a[lane],       w1b_lo = sW1b[lane];
    float w1a_hi = sW1a[lane + 32],  w1b_hi = sW1b[lane + 32];
    float b1_lo  = sPb1[lane],       b1_hi  = sPb1[lane + 32];
    float b2_lo  = sPb2[lane],       b2_hi  = sPb2[lane + 32];
    float w_lo   = sw[lane],         w_hi   = sw[lane + 32];
    float cfold = sScal[0], db0 = sScal[1], tb30 = sScal[2];

    float t1 = t[b];
    float h = t1 * (1.0f / (float)NSEG);

    // ---- Per-warp g-grid tabulation: 5 batches of 4 points
    for (int batch = 0; batch < 5; ++batch) {
        int j4 = batch * 4;
        float taus[4];
        #pragma unroll
        for (int s = 0; s < 4; ++s) taus[s] = (float)(j4 + s - 1) * h;

        float h1lo[4], h1hi[4];
        #pragma unroll
        for (int s = 0; s < 4; ++s) {
            h1lo[s] = fast_tanh(fmaf(w1a_lo, t1, fmaf(w1b_lo, taus[s], b1_lo)));
            h1hi[s] = fast_tanh(fmaf(w1a_hi, t1, fmaf(w1b_hi, taus[s], b1_hi)));
        }
        float acc_lo[4], acc_hi[4];
        #pragma unroll
        for (int s = 0; s < 4; ++s) { acc_lo[s] = b2_lo; acc_hi[s] = b2_hi; }

        #pragma unroll 4
        for (int k = 0; k < 32; ++k) {
            float alo[4], ahi[4];
            #pragma unroll
            for (int s = 0; s < 4; ++s) {
                alo[s] = __shfl_sync(0xffffffffu, h1lo[s], k);
                ahi[s] = __shfl_sync(0xffffffffu, h1hi[s], k);
            }
            float wA = sW2T[k * 65 + lane];
            float wB = sW2T[(k + 32) * 65 + lane];
            float wC = sW2T[k * 65 + lane + 32];
            float wD = sW2T[(k + 32) * 65 + lane + 32];
            #pragma unroll
            for (int s = 0; s < 4; ++s) {
                acc_lo[s] = fmaf(wA, alo[s], fmaf(wB, ahi[s], acc_lo[s]));
                acc_hi[s] = fmaf(wC, alo[s], fmaf(wD, ahi[s], acc_hi[s]));
            }
        }
        #pragma unroll
        for (int s = 0; s < 4; ++s) {
            float v = fmaf(w_lo, fast_tanh(acc_lo[s]), w_hi * fast_tanh(acc_hi[s]));
            v = warp_sum(v) + cfold;
            if (lane == 0) sG[warp][j4 + s] = v;
        }
    }
    __syncwarp();
    const float* sGw = sG[warp];

    float ta  = sT1a[lane], tbw = sT1b[lane], tb1r = sTb1[lane];
    float tb2r = sTb2[lane], tw3r = sTw3[lane];

    const float C2 = 0.2f, C3 = 0.3f, C4 = 0.8f, C5 = (float)(8.0 / 9.0);
    const float A21 = 0.2f;
    const float A31 = (float)(3.0 / 40.0),   A32 = (float)(9.0 / 40.0);
    const float A41 = (float)(44.0 / 45.0),  A42 = (float)(-56.0 / 15.0), A43 = (float)(32.0 / 9.0);
    const float A51 = (float)(19372.0 / 6561.0), A52 = (float)(-25360.0 / 2187.0);
    const float A53 = (float)(64448.0 / 6561.0), A54 = (float)(-212.0 / 729.0);
    const float A61 = (float)(9017.0 / 3168.0),  A62 = (float)(-355.0 / 33.0);
    const float A63 = (float)(46732.0 / 5247.0), A64 = (float)(49.0 / 176.0);
    const float A65 = (float)(-5103.0 / 18656.0);
    const float B1 = (float)(35.0 / 384.0), B3 = (float)(500.0 / 1113.0);
    const float B4 = (float)(125.0 / 192.0), B5 = (float)(-2187.0 / 6784.0);
    const float B6 = (float)(11.0 / 84.0);
    const float E1 = (float)(35.0 / 384.0 - 5179.0 / 57600.0);
    const float E3 = (float)(500.0 / 1113.0 - 7571.0 / 16695.0);
    const float E4 = (float)(125.0 / 192.0 - 393.0 / 640.0);
    const float E5 = (float)(-2187.0 / 6784.0 + 92097.0 / 339200.0);
    const float E6 = (float)(11.0 / 84.0 - 187.0 / 2100.0);
    const float E7 = (float)(-1.0 / 40.0);
    const float RTOL = 1e-3f, ATOL = 1e-6f;
    const float SAFETY = 0.9f, FMIN = 0.2f, FMAX = 10.0f;

    float inv_h = __fdividef((float)NSEG, t1);
    float tau = 0.0f, y = 0.0f, dt = 0.01f;

    // FSAL: f1 = theta(tau, y); updated via the f7 hand-off on accept.
    float f1 = theta_eval(tb1r, 0.0f, tbw, tb2r, tw3r, sT2T, lane) + tb30;

    for (int it = 0; it < MAX_STEPS; ++it) {
        float remaining = t1 - tau;
        if (remaining <= 1e-10f) break;
        float dt_eff = fminf(dt, remaining);

        float taus[6];
        taus[0] = tau;
        taus[1] = tau + C2 * dt_eff;
        taus[2] = tau + C3 * dt_eff;
        taus[3] = tau + C4 * dt_eff;
        taus[4] = tau + C5 * dt_eff;
        taus[5] = tau + dt_eff;

        float g[6];
        #pragma unroll
        for (int s = 0; s < 6; ++s) g[s] = g_interp(sGw, taus[s], inv_h);

        float pre[6];
        #pragma unroll
        for (int s = 0; s < 6; ++s) pre[s] = fmaf(ta, taus[s], tb1r);

        float k1 = fmaf(g[0], f1, db0);

        float y2 = fmaf(dt_eff, A21 * k1, y);
        float f2 = theta_eval(pre[1], y2, tbw, tb2r, tw3r, sT2T, lane) + tb30;
        float k2 = fmaf(g[1], f2, db0);

        float y3 = fmaf(dt_eff, fmaf(A31, k1, A32 * k2), y);
        float f3 = theta_eval(pre[2], y3, tbw, tb2r, tw3r, sT2T, lane) + tb30;
        float k3 = fmaf(g[2], f3, db0);

        float y4 = fmaf(dt_eff, fmaf(A41, k1, fmaf(A42, k2, A43 * k3)), y);
        float f4 = theta_eval(pre[3], y4, tbw, tb2r, tw3r, sT2T, lane) + tb30;
        float k4 = fmaf(g[3], f4, db0);

        float y5i = fmaf(dt_eff, fmaf(A51, k1, fmaf(A52, k2, fmaf(A53, k3, A54 * k4))), y);
        float f5 = theta_eval(pre[4], y5i, tbw, tb2r, tw3r, sT2T, lane) + tb30;
        float k5 = fmaf(g[4], f5, db0);

        float y6 = fmaf(dt_eff, fmaf(A61, k1, fmaf(A62, k2, fmaf(A63, k3, fmaf(A64, k4, A65 * k5)))), y);
        float f6 = theta_eval(pre[5], y6, tbw, tb2r, tw3r, sT2T, lane) + tb30;
        float k6 = fmaf(g[5], f6, db0);

        float y5 = fmaf(dt_eff,
                        fmaf(B1, k1, fmaf(B3, k3, fmaf(B4, k4, fmaf(B5, k5, B6 * k6)))),
                        y);
        float f7 = theta_eval(pre[5], y5, tbw, tb2r, tw3r, sT2T, lane) + tb30;
        float k7 = fmaf(g[5], f7, db0);

        float err = dt_eff *
            fmaf(E1, k1, fmaf(E3, k3, fmaf(E4, k4, fmaf(E5, k5, fmaf(E6, k6, E7 * k7)))));
        float scale = fmaf(RTOL, fmaxf(fabsf(y), fabsf(y5)), ATOL);
        float r = __fdividef(err, scale);
        float err_norm = sqrtf(fmaf(r, r, 1e-30f));

        bool accept = (err_norm <= 1.0f);
        float en = fmaxf(err_norm, 1e-10f);
        float factor = SAFETY * exp2f(-0.2f * __log2f(en));
        factor = fminf(fmaxf(factor, FMIN), FMAX);

        if (accept) {
            tau = tau + dt_eff;
            y = y5;
            f1 = f7;   // FSAL hand-off
        }
        dt = fmaxf(dt_eff * factor, 1e-8f);
    }

    if (lane == 0) out[b] = y;
}

extern "C" void kernel_launch(void* const* d_in, const int* in_sizes, int n_in,
                              void* d_out, int out_size) {
    const float* t    = (const float*)d_in[0];
    const float* pW1  = (const float*)d_in[1];
    const float* pb1  = (const float*)d_in[2];
    const float* pW2  = (const float*)d_in[3];
    const float* pb2  = (const float*)d_in[4];
    const float* pW3  = (const float*)d_in[5];
    const float* pb3  = (const float*)d_in[6];
    const float* dW   = (const float*)d_in[7];
    const float* db   = (const float*)d_in[8];
    const float* tW1  = (const float*)d_in[9];
    const float* tb1  = (const float*)d_in[10];
    const float* tW2  = (const float*)d_in[11];
    const float* tb2  = (const float*)d_in[12];
    const float* tW3  = (const float*)d_in[13];
    const float* tb3  = (const float*)d_in[14];
    float* out = (float*)d_out;

    neural_ode_kernel<<<BATCH / WARPS_PER_BLOCK, BLOCK>>>(
        t, pW1, pb1, pW2, pb2, pW3, pb3, dW, db,
        tW1, tb1, tW2, tb2, tW3, tb3, out);
}